// round 4
// baseline (speedup 1.0000x reference)
#include <cuda_runtime.h>
#include <cstdint>

// KatiesDecoder: out[b, v, u*128:(u+1)*128] = z_prime[b, index[v,u], :]
// z_prime (4, 40962, 128) f32; index (163842, 3) int32; x_ancil unused.
// Output: (4, 163842, 384) f32.
//
// One warp per (b, vertex-pair): 6 independent gathered LDG.128 (MLP=6) +
// 6 contiguous STG.128 with streaming hint (keep L2 for z_prime: 21 MB/batch).

static constexpr int B  = 4;
static constexpr int ND = 40962;   // n_dual
static constexpr int D  = 128;     // d_lat
static constexpr int V  = 163842;  // n_vertex (even -> exact pairs)
static constexpr int NU = 3;
static constexpr int VEC = D / 4;  // 32 float4 per latent row

static constexpr int Z_ELEMS   = B * ND * D;  // 20,972,544
static constexpr int IDX_ELEMS = V * NU;      // 491,526

static constexpr int PAIRS = V / 2;           // 81,921
static constexpr int WARPS_PER_BLOCK = 8;
static constexpr int THREADS = WARPS_PER_BLOCK * 32;

__global__ void __launch_bounds__(THREADS)
katies_gather_kernel(const float4* __restrict__ z,   // (B, ND, 32) float4
                     const int2*  __restrict__ idx2, // (V*NU/2) int2, 8B-aligned
                     float4* __restrict__ out)       // (B, V, 96) float4
{
    const int pair = blockIdx.x * WARPS_PER_BLOCK + (threadIdx.x >> 5);
    if (pair >= PAIRS) return;
    const int b = blockIdx.y;
    const int lane = threadIdx.x & 31;

    // 6 indices for vertices (2*pair, 2*pair+1): 3 aligned int2 loads.
    const int2* ip = idx2 + pair * 3;          // byte offset 24*pair, 8B aligned
    const int2 p0 = __ldg(ip + 0);             // j[v0,0], j[v0,1]
    const int2 p1 = __ldg(ip + 1);             // j[v0,2], j[v1,0]
    const int2 p2 = __ldg(ip + 2);             // j[v1,1], j[v1,2]

    // 6 independent gathered row reads (mostly L2 hits).
    const float4* zb = z + (long long)b * ND * VEC + lane;
    const float4 a0 = __ldg(zb + (long long)p0.x * VEC);
    const float4 a1 = __ldg(zb + (long long)p0.y * VEC);
    const float4 a2 = __ldg(zb + (long long)p1.x * VEC);
    const float4 a3 = __ldg(zb + (long long)p1.y * VEC);
    const float4 a4 = __ldg(zb + (long long)p2.x * VEC);
    const float4 a5 = __ldg(zb + (long long)p2.y * VEC);

    // One contiguous 3072 B destination span per warp (192 float4).
    float4* dst = out + ((long long)b * V + (long long)pair * 2) * (NU * VEC) + lane;
    __stcs(dst + 0 * VEC, a0);
    __stcs(dst + 1 * VEC, a1);
    __stcs(dst + 2 * VEC, a2);
    __stcs(dst + 3 * VEC, a3);
    __stcs(dst + 4 * VEC, a4);
    __stcs(dst + 5 * VEC, a5);
}

extern "C" void kernel_launch(void* const* d_in, const int* in_sizes, int n_in,
                              void* d_out, int out_size)
{
    // Bind inputs by element count (robust to ordering surprises).
    const void* z_ptr   = d_in[0];
    const void* idx_ptr = d_in[2];
    for (int i = 0; i < n_in; i++) {
        if (in_sizes[i] == Z_ELEMS)   z_ptr   = d_in[i];
        if (in_sizes[i] == IDX_ELEMS) idx_ptr = d_in[i];
    }

    const float4* z    = (const float4*)z_ptr;
    const int2*   idx2 = (const int2*)idx_ptr;
    float4*       out  = (float4*)d_out;

    dim3 grid((PAIRS + WARPS_PER_BLOCK - 1) / WARPS_PER_BLOCK, B);
    katies_gather_kernel<<<grid, THREADS>>>(z, idx2, out);
}